// round 15
// baseline (speedup 1.0000x reference)
#include <cuda_runtime.h>
#include <cooperative_groups.h>

namespace cg = cooperative_groups;
typedef unsigned long long ull;

#define WW 256           // matrix width (dustbin handled analytically)
#define RPC 64           // rows per CTA (cluster of 4 covers 256)
#define NTHREADS 512
#define NWARPS 16
#define CSZ 4
#define SK_ITERS 10

// ---- packed f32x2 helpers (B300 FFMA2 pipe; ptxas won't auto-fuse) ----
__device__ __forceinline__ ull pk2(float lo, float hi) {
    ull r; asm("mov.b64 %0, {%1,%2};" : "=l"(r) : "f"(lo), "f"(hi)); return r;
}
__device__ __forceinline__ void upk2(ull v, float& lo, float& hi) {
    asm("mov.b64 {%0,%1}, %2;" : "=f"(lo), "=f"(hi) : "l"(v));
}
__device__ __forceinline__ ull fma2(ull a, ull b, ull c) {
    ull d; asm("fma.rn.f32x2 %0, %1, %2, %3;" : "=l"(d) : "l"(a), "l"(b), "l"(c)); return d;
}
__device__ __forceinline__ ull mul2(ull a, ull b) {
    ull d; asm("mul.rn.f32x2 %0, %1, %2;" : "=l"(d) : "l"(a), "l"(b)); return d;
}
__device__ __forceinline__ ull add2(ull a, ull b) {
    ull d; asm("add.rn.f32x2 %0, %1, %2;" : "=l"(d) : "l"(a), "l"(b)); return d;
}

// ---- cluster DSMEM helpers (u32 addressing to save registers) ----
__device__ __forceinline__ unsigned smem_u32(const void* p) {
    unsigned a;
    asm("{.reg .u64 t; cvta.to.shared.u64 t, %1; cvt.u32.u64 %0, t;}" : "=r"(a) : "l"(p));
    return a;
}
__device__ __forceinline__ unsigned mapa_rank(unsigned addr, unsigned r) {
    unsigned d; asm("mapa.shared::cluster.u32 %0, %1, %2;" : "=r"(d) : "r"(addr), "r"(r));
    return d;
}
__device__ __forceinline__ ull ldsc64(unsigned a) {
    ull v; asm volatile("ld.shared::cluster.b64 %0, [%1];" : "=l"(v) : "r"(a)); return v;
}
__device__ __forceinline__ float ldsc32(unsigned a) {
    float v; asm volatile("ld.shared::cluster.b32 %0, [%1];" : "=f"(v) : "r"(a)); return v;
}

struct __align__(16) Smem {
    float temp[NWARPS][WW];  // per-warp colsum partials   16384 B
    float expt[2][264];      // export: [0..255]=col partial, [256]=sumA (dbl-buffered)
    float b[WW];             // current b (exp(v)) — identical on all ranks
    float a[RPC];            // current a (exp(u)) for own rows
    float wsum[4];           // deterministic sumB pieces (4 warps of 128 threads)
    float bW;                // dustbin b
    float aW;                // dustbin a
};

__global__ void __launch_bounds__(NTHREADS, 2) __cluster_dims__(CSZ, 1, 1)
sinkhorn_disp_kernel(const float* __restrict__ attn,
                     const float* __restrict__ phi,
                     float* __restrict__ out,
                     int out_half)
{
    __shared__ Smem sm;

    cg::cluster_group cluster = cg::this_cluster();
    const unsigned rank = cluster.block_rank();      // 0..3
    const unsigned m    = blockIdx.x >> 2;           // (n*H + h)
    const int tid  = threadIdx.x;
    const int lane = tid & 31;
    const int warp = tid >> 5;
    const float p     = __expf(phi[0]);              // dustbin kernel exp(phi)
    const float inv2w = 1.0f / 512.0f;               // mu/nu for real rows/cols

    // DSMEM addresses of every rank's export buffer (fixed summation order)
    const unsigned e_local = smem_u32(&sm.expt[0][0]);
    unsigned eaddr[CSZ];
    #pragma unroll
    for (int r = 0; r < CSZ; ++r) eaddr[r] = mapa_rank(e_local, r);

    // ---- Phase 0: K = exp(sim) into registers (4 rows x 8 cols per thread) ----
    // Rows: warp*4..+3 within this CTA's 64-row block.
    // Cols: A = [lane*4, +4), B = [128+lane*4, +4); packed as f32x2 pairs.
    ull kA01[4], kA23[4], kB01[4], kB23[4];          // 32 regs of K data
    {
        const float4* base = reinterpret_cast<const float4*>(
            attn + (size_t)m * WW * WW + ((size_t)rank * RPC + warp * 4) * WW);
        #pragma unroll
        for (int h = 0; h < 2; ++h) {                // 2 batches of 4 LDG.128
            float4 t[4];
            #pragma unroll
            for (int r2 = 0; r2 < 2; ++r2) {
                int rr = h * 2 + r2;
                t[r2 * 2]     = base[rr * 64 + lane];
                t[r2 * 2 + 1] = base[rr * 64 + 32 + lane];
            }
            #pragma unroll
            for (int r2 = 0; r2 < 2; ++r2) {
                int rr = h * 2 + r2;
                kA01[rr] = pk2(__expf(t[r2*2].x),   __expf(t[r2*2].y));
                kA23[rr] = pk2(__expf(t[r2*2].z),   __expf(t[r2*2].w));
                kB01[rr] = pk2(__expf(t[r2*2+1].x), __expf(t[r2*2+1].y));
                kB23[rr] = pk2(__expf(t[r2*2+1].z), __expf(t[r2*2+1].w));
            }
        }
    }
    if (tid < RPC) sm.a[tid] = 1.0f;
    if (tid == 0)  sm.aW = 1.0f;

    // ---- Initial colsum partials with a = 1 ----
    {
        ull cA01 = 0, cA23 = 0, cB01 = 0, cB23 = 0;
        #pragma unroll
        for (int rr = 0; rr < 4; ++rr) {
            cA01 = add2(cA01, kA01[rr]); cA23 = add2(cA23, kA23[rr]);
            cB01 = add2(cB01, kB01[rr]); cB23 = add2(cB23, kB23[rr]);
        }
        *(ull*)&sm.temp[warp][lane*4]       = cA01;
        *(ull*)&sm.temp[warp][lane*4 + 2]   = cA23;
        *(ull*)&sm.temp[warp][lane*4 + 128] = cB01;
        *(ull*)&sm.temp[warp][lane*4 + 130] = cB23;
    }
    __syncthreads();

    // ---- Sinkhorn iterations ----
    for (int t = 1; t <= SK_ITERS; ++t) {
        const int  buf  = t & 1;
        const bool last = (t == SK_ITERS);

        // step 1: cross-warp colsum reduce (packed, 128 threads); export + sumA
        if (tid < 128) {
            ull mp = 0;
            #pragma unroll
            for (int w = 0; w < NWARPS; ++w)
                mp = add2(mp, *(const ull*)&sm.temp[w][2 * tid]);
            *(ull*)&sm.expt[buf][2 * tid] = mp;
        } else if (tid < 160) {                       // warp 4: sumA over own 64 a's
            int l = tid - 128;
            float s = sm.a[l] + sm.a[l + 32];
            #pragma unroll
            for (int o = 16; o; o >>= 1) s += __shfl_down_sync(0xffffffffu, s, o);
            if (l == 0) sm.expt[buf][WW] = s;
        }
        asm volatile("barrier.cluster.arrive.aligned;" ::: "memory");
        asm volatile("barrier.cluster.wait.aligned;"   ::: "memory");

        // step 2: full colsum over 4 ranks (fixed order) + dustbin; b = nu/colsum
        const float aWv = sm.aW;
        if (tid < 128) {
            const unsigned off = (unsigned)buf * 1056u + (unsigned)tid * 8u;
            ull c01 = add2(add2(ldsc64(eaddr[0] + off), ldsc64(eaddr[1] + off)),
                           add2(ldsc64(eaddr[2] + off), ldsc64(eaddr[3] + off)));
            float clo, chi; upk2(c01, clo, chi);
            float paw = p * aWv;
            float b0 = __fdividef(inv2w, clo + paw);
            float b1 = __fdividef(inv2w, chi + paw);
            *(ull*)&sm.b[2 * tid] = pk2(b0, b1);
            float s = b0 + b1;
            #pragma unroll
            for (int o = 16; o; o >>= 1) s += __shfl_down_sync(0xffffffffu, s, o);
            if (lane == 0) sm.wsum[warp] = s;
        } else if (tid == 128) {                      // dustbin column
            const unsigned offA = (unsigned)buf * 1056u + 1024u;
            float sumA = (ldsc32(eaddr[0] + offA) + ldsc32(eaddr[1] + offA)) +
                         (ldsc32(eaddr[2] + offA) + ldsc32(eaddr[3] + offA));
            sm.bW = 0.5f / (p * (sumA + aWv));
        }
        __syncthreads();
        if (tid == 0) {                               // dustbin row -> next aW
            float sb = (sm.wsum[0] + sm.wsum[1]) + (sm.wsum[2] + sm.wsum[3]);
            sm.aW = 0.5f / (p * (sb + sm.bW));
        }

        // step 3: register sweep: rowsum -> a[i]; next colsum partials
        const float pbW = p * sm.bW;
        ull bA01 = *(const ull*)&sm.b[lane*4];
        ull bA23 = *(const ull*)&sm.b[lane*4 + 2];
        ull bB01 = *(const ull*)&sm.b[lane*4 + 128];
        ull bB23 = *(const ull*)&sm.b[lane*4 + 130];

        if (!last) {
            ull cA01 = 0, cA23 = 0, cB01 = 0, cB23 = 0;
            #pragma unroll
            for (int rr = 0; rr < 4; ++rr) {
                int i = warp * 4 + rr;
                ull r01 = mul2(kA01[rr], bA01);
                r01 = fma2(kB01[rr], bB01, r01);
                ull r23 = mul2(kA23[rr], bA23);
                r23 = fma2(kB23[rr], bB23, r23);
                float rlo, rhi; upk2(add2(r01, r23), rlo, rhi);
                float rs = rlo + rhi;
                #pragma unroll
                for (int o = 16; o; o >>= 1) rs += __shfl_xor_sync(0xffffffffu, rs, o);
                float ai = __fdividef(inv2w, rs + pbW);
                if (lane == 0) sm.a[i] = ai;
                ull ai2 = pk2(ai, ai);
                cA01 = fma2(kA01[rr], ai2, cA01);
                cA23 = fma2(kA23[rr], ai2, cA23);
                cB01 = fma2(kB01[rr], ai2, cB01);
                cB23 = fma2(kB23[rr], ai2, cB23);
            }
            *(ull*)&sm.temp[warp][lane*4]       = cA01;
            *(ull*)&sm.temp[warp][lane*4 + 2]   = cA23;
            *(ull*)&sm.temp[warp][lane*4 + 128] = cB01;
            *(ull*)&sm.temp[warp][lane*4 + 130] = cB23;
        } else {
            // final iteration: argmax + 3-tap soft-argmax readout
            #pragma unroll
            for (int rr = 0; rr < 4; ++rr) {
                int i  = warp * 4 + rr;
                int ig = (int)rank * RPC + i;
                float va0, va1, va2, va3, vb0, vb1, vb2, vb3;
                upk2(mul2(kA01[rr], bA01), va0, va1);
                upk2(mul2(kA23[rr], bA23), va2, va3);
                upk2(mul2(kB01[rr], bB01), vb0, vb1);
                upk2(mul2(kB23[rr], bB23), vb2, vb3);
                float rs = ((va0 + va1) + (va2 + va3)) + ((vb0 + vb1) + (vb2 + vb3));
                #pragma unroll
                for (int o = 16; o; o >>= 1) rs += __shfl_xor_sync(0xffffffffu, rs, o);
                float ai = __fdividef(inv2w, rs + pbW);

                float best = va0; int bestj = lane * 4;
                if (va1 > best) { best = va1; bestj = lane*4 + 1; }
                if (va2 > best) { best = va2; bestj = lane*4 + 2; }
                if (va3 > best) { best = va3; bestj = lane*4 + 3; }
                int jb = lane * 4 + 128;
                if (vb0 > best) { best = vb0; bestj = jb;     }
                if (vb1 > best) { best = vb1; bestj = jb + 1; }
                if (vb2 > best) { best = vb2; bestj = jb + 2; }
                if (vb3 > best) { best = vb3; bestj = jb + 3; }
                #pragma unroll
                for (int o = 16; o; o >>= 1) {        // first-index tie-break
                    float ov = __shfl_xor_sync(0xffffffffu, best, o);
                    int   oj = __shfl_xor_sync(0xffffffffu, bestj, o);
                    if (ov > best || (ov == best && oj < bestj)) { best = ov; bestj = oj; }
                }

                float scale = ai * 512.0f;            // attn = 2w * a_i * (K*b)
                float nl = 0.0f, dl = 0.0f;
                #pragma unroll
                for (int d = -1; d <= 1; ++d) {
                    int jj = bestj + d;
                    if (jj < 0 || jj >= WW) continue;
                    int cA = jj - lane * 4;
                    int cB = jj - 128 - lane * 4;
                    float v = 0.0f; bool own = false;
                    if (cA >= 0 && cA < 4) {
                        v = (cA == 0) ? va0 : (cA == 1) ? va1 : (cA == 2) ? va2 : va3;
                        own = true;
                    } else if (cB >= 0 && cB < 4) {
                        v = (cB == 0) ? vb0 : (cB == 1) ? vb1 : (cB == 2) ? vb2 : vb3;
                        own = true;
                    }
                    if (own) {
                        float av = v * scale;
                        nl += av;
                        dl += av * fmaxf((float)(ig - jj), 0.0f);
                    }
                }
                #pragma unroll
                for (int o = 16; o; o >>= 1) {
                    nl += __shfl_xor_sync(0xffffffffu, nl, o);
                    dl += __shfl_xor_sync(0xffffffffu, dl, o);
                }
                if (lane == 0) {
                    float normc = (nl < 0.1f) ? 1.0f : nl;
                    size_t o0 = (size_t)m * WW + (size_t)ig;
                    out[o0] = __fdividef(dl, normc);              // disp
                    out[(size_t)out_half + o0] = 1.0f - normc;    // occ
                }
            }
        }
        __syncthreads();
    }

    // keep smem alive until peers finish their last DSMEM reads
    asm volatile("barrier.cluster.arrive.aligned;" ::: "memory");
    asm volatile("barrier.cluster.wait.aligned;"   ::: "memory");
}

extern "C" void kernel_launch(void* const* d_in, const int* in_sizes, int n_in,
                              void* d_out, int out_size) {
    const float* attn = (const float*)d_in[0];
    const float* phi  = (const float*)d_in[1];
    float* out        = (float*)d_out;

    int NH = in_sizes[0] / (WW * WW);           // 480 matrices
    sinkhorn_disp_kernel<<<CSZ * NH, NTHREADS>>>(attn, phi, out, out_size / 2);
}

// round 16
// speedup vs baseline: 1.0008x; 1.0008x over previous
#include <cuda_runtime.h>
#include <cooperative_groups.h>

namespace cg = cooperative_groups;
typedef unsigned long long ull;

#define WW 256           // matrix width (dustbin handled analytically)
#define RPC 64           // rows per CTA (cluster of 4 covers 256)
#define NTHREADS 512
#define NWARPS 16
#define CSZ 4
#define SK_ITERS 10

// ---- packed f32x2 helpers (B300 FFMA2 pipe; ptxas won't auto-fuse) ----
__device__ __forceinline__ ull pk2(float lo, float hi) {
    ull r; asm("mov.b64 %0, {%1,%2};" : "=l"(r) : "f"(lo), "f"(hi)); return r;
}
__device__ __forceinline__ void upk2(ull v, float& lo, float& hi) {
    asm("mov.b64 {%0,%1}, %2;" : "=f"(lo), "=f"(hi) : "l"(v));
}
__device__ __forceinline__ ull fma2(ull a, ull b, ull c) {
    ull d; asm("fma.rn.f32x2 %0, %1, %2, %3;" : "=l"(d) : "l"(a), "l"(b), "l"(c)); return d;
}
__device__ __forceinline__ ull mul2(ull a, ull b) {
    ull d; asm("mul.rn.f32x2 %0, %1, %2;" : "=l"(d) : "l"(a), "l"(b)); return d;
}
__device__ __forceinline__ ull add2(ull a, ull b) {
    ull d; asm("add.rn.f32x2 %0, %1, %2;" : "=l"(d) : "l"(a), "l"(b)); return d;
}

// ---- cluster DSMEM helpers (u32 addressing to save registers) ----
__device__ __forceinline__ unsigned smem_u32(const void* p) {
    unsigned a;
    asm("{.reg .u64 t; cvta.to.shared.u64 t, %1; cvt.u32.u64 %0, t;}" : "=r"(a) : "l"(p));
    return a;
}
__device__ __forceinline__ unsigned mapa_rank(unsigned addr, unsigned r) {
    unsigned d; asm("mapa.shared::cluster.u32 %0, %1, %2;" : "=r"(d) : "r"(addr), "r"(r));
    return d;
}
__device__ __forceinline__ ull ldsc64(unsigned a) {
    ull v; asm volatile("ld.shared::cluster.b64 %0, [%1];" : "=l"(v) : "r"(a)); return v;
}
__device__ __forceinline__ float ldsc32(unsigned a) {
    float v; asm volatile("ld.shared::cluster.b32 %0, [%1];" : "=f"(v) : "r"(a)); return v;
}

struct __align__(16) Smem {
    float temp[NWARPS][WW];  // per-warp colsum partials   16384 B
    float expt[2][264];      // export: [0..255]=col partial, [256]=sumA (dbl-buffered)
    float b[WW];             // current b (exp(v)) — identical on all ranks
    float a[RPC];            // current a (exp(u)) for own rows
    float wsum[4];           // deterministic sumB pieces (4 warps of 128 threads)
    float bW;                // dustbin b
    float aW;                // dustbin a
};

__global__ void __launch_bounds__(NTHREADS, 2) __cluster_dims__(CSZ, 1, 1)
sinkhorn_disp_kernel(const float* __restrict__ attn,
                     const float* __restrict__ phi,
                     float* __restrict__ out,
                     int out_half)
{
    __shared__ Smem sm;

    cg::cluster_group cluster = cg::this_cluster();
    const unsigned rank = cluster.block_rank();      // 0..3
    const unsigned m    = blockIdx.x >> 2;           // (n*H + h)
    const int tid  = threadIdx.x;
    const int lane = tid & 31;
    const int warp = tid >> 5;
    const float p     = __expf(phi[0]);              // dustbin kernel exp(phi)
    const float inv2w = 1.0f / 512.0f;               // mu/nu for real rows/cols

    // DSMEM addresses of every rank's export buffer (fixed summation order)
    const unsigned e_local = smem_u32(&sm.expt[0][0]);
    unsigned eaddr[CSZ];
    #pragma unroll
    for (int r = 0; r < CSZ; ++r) eaddr[r] = mapa_rank(e_local, r);

    // ---- Phase 0: K = exp(sim) into registers (4 rows x 8 cols per thread) ----
    // Rows: warp*4..+3 within this CTA's 64-row block.
    // Cols: A = [lane*4, +4), B = [128+lane*4, +4); packed as f32x2 pairs.
    ull kA01[4], kA23[4], kB01[4], kB23[4];          // 32 regs of K data
    {
        const float4* base = reinterpret_cast<const float4*>(
            attn + (size_t)m * WW * WW + ((size_t)rank * RPC + warp * 4) * WW);
        #pragma unroll
        for (int h = 0; h < 2; ++h) {                // 2 batches of 4 LDG.128
            float4 t[4];
            #pragma unroll
            for (int r2 = 0; r2 < 2; ++r2) {
                int rr = h * 2 + r2;
                t[r2 * 2]     = base[rr * 64 + lane];
                t[r2 * 2 + 1] = base[rr * 64 + 32 + lane];
            }
            #pragma unroll
            for (int r2 = 0; r2 < 2; ++r2) {
                int rr = h * 2 + r2;
                kA01[rr] = pk2(__expf(t[r2*2].x),   __expf(t[r2*2].y));
                kA23[rr] = pk2(__expf(t[r2*2].z),   __expf(t[r2*2].w));
                kB01[rr] = pk2(__expf(t[r2*2+1].x), __expf(t[r2*2+1].y));
                kB23[rr] = pk2(__expf(t[r2*2+1].z), __expf(t[r2*2+1].w));
            }
        }
    }
    if (tid < RPC) sm.a[tid] = 1.0f;
    if (tid == 0)  sm.aW = 1.0f;

    // ---- Initial colsum partials with a = 1 ----
    {
        ull cA01 = 0, cA23 = 0, cB01 = 0, cB23 = 0;
        #pragma unroll
        for (int rr = 0; rr < 4; ++rr) {
            cA01 = add2(cA01, kA01[rr]); cA23 = add2(cA23, kA23[rr]);
            cB01 = add2(cB01, kB01[rr]); cB23 = add2(cB23, kB23[rr]);
        }
        *(ull*)&sm.temp[warp][lane*4]       = cA01;
        *(ull*)&sm.temp[warp][lane*4 + 2]   = cA23;
        *(ull*)&sm.temp[warp][lane*4 + 128] = cB01;
        *(ull*)&sm.temp[warp][lane*4 + 130] = cB23;
    }
    __syncthreads();

    // ---- Sinkhorn iterations ----
    for (int t = 1; t <= SK_ITERS; ++t) {
        const int  buf  = t & 1;
        const bool last = (t == SK_ITERS);

        // step 1: cross-warp colsum reduce (packed, 128 threads); export + sumA
        if (tid < 128) {
            ull mp = 0;
            #pragma unroll
            for (int w = 0; w < NWARPS; ++w)
                mp = add2(mp, *(const ull*)&sm.temp[w][2 * tid]);
            *(ull*)&sm.expt[buf][2 * tid] = mp;
        } else if (tid < 160) {                       // warp 4: sumA over own 64 a's
            int l = tid - 128;
            float s = sm.a[l] + sm.a[l + 32];
            #pragma unroll
            for (int o = 16; o; o >>= 1) s += __shfl_down_sync(0xffffffffu, s, o);
            if (l == 0) sm.expt[buf][WW] = s;
        }
        asm volatile("barrier.cluster.arrive.aligned;" ::: "memory");
        asm volatile("barrier.cluster.wait.aligned;"   ::: "memory");

        // step 2: full colsum over 4 ranks (fixed order) + dustbin; b = nu/colsum
        const float aWv = sm.aW;
        if (tid < 128) {
            const unsigned off = (unsigned)buf * 1056u + (unsigned)tid * 8u;
            ull c01 = add2(add2(ldsc64(eaddr[0] + off), ldsc64(eaddr[1] + off)),
                           add2(ldsc64(eaddr[2] + off), ldsc64(eaddr[3] + off)));
            float clo, chi; upk2(c01, clo, chi);
            float paw = p * aWv;
            float b0 = __fdividef(inv2w, clo + paw);
            float b1 = __fdividef(inv2w, chi + paw);
            *(ull*)&sm.b[2 * tid] = pk2(b0, b1);
            float s = b0 + b1;
            #pragma unroll
            for (int o = 16; o; o >>= 1) s += __shfl_down_sync(0xffffffffu, s, o);
            if (lane == 0) sm.wsum[warp] = s;
        } else if (tid == 128) {                      // dustbin column
            const unsigned offA = (unsigned)buf * 1056u + 1024u;
            float sumA = (ldsc32(eaddr[0] + offA) + ldsc32(eaddr[1] + offA)) +
                         (ldsc32(eaddr[2] + offA) + ldsc32(eaddr[3] + offA));
            sm.bW = 0.5f / (p * (sumA + aWv));
        }
        __syncthreads();
        if (tid == 0) {                               // dustbin row -> next aW
            float sb = (sm.wsum[0] + sm.wsum[1]) + (sm.wsum[2] + sm.wsum[3]);
            sm.aW = 0.5f / (p * (sb + sm.bW));
        }

        // step 3: register sweep: rowsum -> a[i]; next colsum partials
        const float pbW = p * sm.bW;
        ull bA01 = *(const ull*)&sm.b[lane*4];
        ull bA23 = *(const ull*)&sm.b[lane*4 + 2];
        ull bB01 = *(const ull*)&sm.b[lane*4 + 128];
        ull bB23 = *(const ull*)&sm.b[lane*4 + 130];

        if (!last) {
            ull cA01 = 0, cA23 = 0, cB01 = 0, cB23 = 0;
            #pragma unroll
            for (int rr = 0; rr < 4; ++rr) {
                int i = warp * 4 + rr;
                ull r01 = mul2(kA01[rr], bA01);
                r01 = fma2(kB01[rr], bB01, r01);
                ull r23 = mul2(kA23[rr], bA23);
                r23 = fma2(kB23[rr], bB23, r23);
                float rlo, rhi; upk2(add2(r01, r23), rlo, rhi);
                float rs = rlo + rhi;
                #pragma unroll
                for (int o = 16; o; o >>= 1) rs += __shfl_xor_sync(0xffffffffu, rs, o);
                float ai = __fdividef(inv2w, rs + pbW);
                if (lane == 0) sm.a[i] = ai;
                ull ai2 = pk2(ai, ai);
                cA01 = fma2(kA01[rr], ai2, cA01);
                cA23 = fma2(kA23[rr], ai2, cA23);
                cB01 = fma2(kB01[rr], ai2, cB01);
                cB23 = fma2(kB23[rr], ai2, cB23);
            }
            *(ull*)&sm.temp[warp][lane*4]       = cA01;
            *(ull*)&sm.temp[warp][lane*4 + 2]   = cA23;
            *(ull*)&sm.temp[warp][lane*4 + 128] = cB01;
            *(ull*)&sm.temp[warp][lane*4 + 130] = cB23;
        } else {
            // final iteration: argmax + 3-tap soft-argmax readout
            #pragma unroll
            for (int rr = 0; rr < 4; ++rr) {
                int i  = warp * 4 + rr;
                int ig = (int)rank * RPC + i;
                float va0, va1, va2, va3, vb0, vb1, vb2, vb3;
                upk2(mul2(kA01[rr], bA01), va0, va1);
                upk2(mul2(kA23[rr], bA23), va2, va3);
                upk2(mul2(kB01[rr], bB01), vb0, vb1);
                upk2(mul2(kB23[rr], bB23), vb2, vb3);
                float rs = ((va0 + va1) + (va2 + va3)) + ((vb0 + vb1) + (vb2 + vb3));
                #pragma unroll
                for (int o = 16; o; o >>= 1) rs += __shfl_xor_sync(0xffffffffu, rs, o);
                float ai = __fdividef(inv2w, rs + pbW);

                float best = va0; int bestj = lane * 4;
                if (va1 > best) { best = va1; bestj = lane*4 + 1; }
                if (va2 > best) { best = va2; bestj = lane*4 + 2; }
                if (va3 > best) { best = va3; bestj = lane*4 + 3; }
                int jb = lane * 4 + 128;
                if (vb0 > best) { best = vb0; bestj = jb;     }
                if (vb1 > best) { best = vb1; bestj = jb + 1; }
                if (vb2 > best) { best = vb2; bestj = jb + 2; }
                if (vb3 > best) { best = vb3; bestj = jb + 3; }
                #pragma unroll
                for (int o = 16; o; o >>= 1) {        // first-index tie-break
                    float ov = __shfl_xor_sync(0xffffffffu, best, o);
                    int   oj = __shfl_xor_sync(0xffffffffu, bestj, o);
                    if (ov > best || (ov == best && oj < bestj)) { best = ov; bestj = oj; }
                }

                float scale = ai * 512.0f;            // attn = 2w * a_i * (K*b)
                float nl = 0.0f, dl = 0.0f;
                #pragma unroll
                for (int d = -1; d <= 1; ++d) {
                    int jj = bestj + d;
                    if (jj < 0 || jj >= WW) continue;
                    int cA = jj - lane * 4;
                    int cB = jj - 128 - lane * 4;
                    float v = 0.0f; bool own = false;
                    if (cA >= 0 && cA < 4) {
                        v = (cA == 0) ? va0 : (cA == 1) ? va1 : (cA == 2) ? va2 : va3;
                        own = true;
                    } else if (cB >= 0 && cB < 4) {
                        v = (cB == 0) ? vb0 : (cB == 1) ? vb1 : (cB == 2) ? vb2 : vb3;
                        own = true;
                    }
                    if (own) {
                        float av = v * scale;
                        nl += av;
                        dl += av * fmaxf((float)(ig - jj), 0.0f);
                    }
                }
                #pragma unroll
                for (int o = 16; o; o >>= 1) {
                    nl += __shfl_xor_sync(0xffffffffu, nl, o);
                    dl += __shfl_xor_sync(0xffffffffu, dl, o);
                }
                if (lane == 0) {
                    float normc = (nl < 0.1f) ? 1.0f : nl;
                    size_t o0 = (size_t)m * WW + (size_t)ig;
                    out[o0] = __fdividef(dl, normc);              // disp
                    out[(size_t)out_half + o0] = 1.0f - normc;    // occ
                }
            }
        }
        __syncthreads();
    }

    // keep smem alive until peers finish their last DSMEM reads
    asm volatile("barrier.cluster.arrive.aligned;" ::: "memory");
    asm volatile("barrier.cluster.wait.aligned;"   ::: "memory");
}

extern "C" void kernel_launch(void* const* d_in, const int* in_sizes, int n_in,
                              void* d_out, int out_size) {
    const float* attn = (const float*)d_in[0];
    const float* phi  = (const float*)d_in[1];
    float* out        = (float*)d_out;

    int NH = in_sizes[0] / (WW * WW);           // 480 matrices
    sinkhorn_disp_kernel<<<CSZ * NH, NTHREADS>>>(attn, phi, out, out_size / 2);
}

// round 17
// speedup vs baseline: 1.0072x; 1.0064x over previous
#include <cuda_runtime.h>
#include <cooperative_groups.h>

namespace cg = cooperative_groups;
typedef unsigned long long ull;

#define WW 256           // matrix width (dustbin handled analytically)
#define RPC 64           // rows per CTA (cluster of 4 covers 256)
#define NTHREADS 512
#define NWARPS 16
#define CSZ 4
#define SK_ITERS 10

// ---- packed f32x2 helpers (B300 FFMA2 pipe; ptxas won't auto-fuse) ----
__device__ __forceinline__ ull pk2(float lo, float hi) {
    ull r; asm("mov.b64 %0, {%1,%2};" : "=l"(r) : "f"(lo), "f"(hi)); return r;
}
__device__ __forceinline__ void upk2(ull v, float& lo, float& hi) {
    asm("mov.b64 {%0,%1}, %2;" : "=f"(lo), "=f"(hi) : "l"(v));
}
__device__ __forceinline__ ull fma2(ull a, ull b, ull c) {
    ull d; asm("fma.rn.f32x2 %0, %1, %2, %3;" : "=l"(d) : "l"(a), "l"(b), "l"(c)); return d;
}
__device__ __forceinline__ ull mul2(ull a, ull b) {
    ull d; asm("mul.rn.f32x2 %0, %1, %2;" : "=l"(d) : "l"(a), "l"(b)); return d;
}
__device__ __forceinline__ ull add2(ull a, ull b) {
    ull d; asm("add.rn.f32x2 %0, %1, %2;" : "=l"(d) : "l"(a), "l"(b)); return d;
}

// ---- cluster DSMEM helpers (u32 addressing to save registers) ----
__device__ __forceinline__ unsigned smem_u32(const void* p) {
    unsigned a;
    asm("{.reg .u64 t; cvta.to.shared.u64 t, %1; cvt.u32.u64 %0, t;}" : "=r"(a) : "l"(p));
    return a;
}
__device__ __forceinline__ unsigned mapa_rank(unsigned addr, unsigned r) {
    unsigned d; asm("mapa.shared::cluster.u32 %0, %1, %2;" : "=r"(d) : "r"(addr), "r"(r));
    return d;
}
__device__ __forceinline__ ull ldsc64(unsigned a) {
    ull v; asm volatile("ld.shared::cluster.b64 %0, [%1];" : "=l"(v) : "r"(a)); return v;
}
__device__ __forceinline__ float ldsc32(unsigned a) {
    float v; asm volatile("ld.shared::cluster.b32 %0, [%1];" : "=f"(v) : "r"(a)); return v;
}

struct __align__(16) Smem {
    float temp[NWARPS][WW];  // per-warp colsum partials   16384 B
    float expt[2][264];      // export: [0..255]=col partial, [256]=sumA (dbl-buffered)
    float b[WW];             // current b (exp(v)) — identical on all ranks
    float a[RPC];            // current a (exp(u)) for own rows
    float wsum[4];           // deterministic sumB pieces (4 warps of 128 threads)
    float bW;                // dustbin b
    float aW;                // dustbin a
};

__global__ void __launch_bounds__(NTHREADS, 2) __cluster_dims__(CSZ, 1, 1)
sinkhorn_disp_kernel(const float* __restrict__ attn,
                     const float* __restrict__ phi,
                     float* __restrict__ out,
                     int out_half)
{
    __shared__ Smem sm;

    cg::cluster_group cluster = cg::this_cluster();
    const unsigned rank = cluster.block_rank();      // 0..3
    const unsigned m    = blockIdx.x >> 2;           // (n*H + h)
    const int tid  = threadIdx.x;
    const int lane = tid & 31;
    const int warp = tid >> 5;
    const float p     = __expf(phi[0]);              // dustbin kernel exp(phi)
    const float inv2w = 1.0f / 512.0f;               // mu/nu for real rows/cols

    // DSMEM addresses of every rank's export buffer (fixed summation order)
    const unsigned e_local = smem_u32(&sm.expt[0][0]);
    unsigned eaddr[CSZ];
    #pragma unroll
    for (int r = 0; r < CSZ; ++r) eaddr[r] = mapa_rank(e_local, r);

    // ---- Phase 0: K = exp(sim) into registers (4 rows x 8 cols per thread) ----
    // Rows: warp*4..+3 within this CTA's 64-row block.
    // Cols: A = [lane*4, +4), B = [128+lane*4, +4); packed as f32x2 pairs.
    ull kA01[4], kA23[4], kB01[4], kB23[4];          // 32 regs of K data
    {
        const float4* base = reinterpret_cast<const float4*>(
            attn + (size_t)m * WW * WW + ((size_t)rank * RPC + warp * 4) * WW);
        #pragma unroll
        for (int h = 0; h < 2; ++h) {                // 2 batches of 4 LDG.128
            float4 t[4];
            #pragma unroll
            for (int r2 = 0; r2 < 2; ++r2) {
                int rr = h * 2 + r2;
                t[r2 * 2]     = base[rr * 64 + lane];
                t[r2 * 2 + 1] = base[rr * 64 + 32 + lane];
            }
            #pragma unroll
            for (int r2 = 0; r2 < 2; ++r2) {
                int rr = h * 2 + r2;
                kA01[rr] = pk2(__expf(t[r2*2].x),   __expf(t[r2*2].y));
                kA23[rr] = pk2(__expf(t[r2*2].z),   __expf(t[r2*2].w));
                kB01[rr] = pk2(__expf(t[r2*2+1].x), __expf(t[r2*2+1].y));
                kB23[rr] = pk2(__expf(t[r2*2+1].z), __expf(t[r2*2+1].w));
            }
        }
    }
    if (tid < RPC) sm.a[tid] = 1.0f;
    if (tid == 0)  sm.aW = 1.0f;

    // ---- Initial colsum partials with a = 1 ----
    {
        ull cA01 = 0, cA23 = 0, cB01 = 0, cB23 = 0;
        #pragma unroll
        for (int rr = 0; rr < 4; ++rr) {
            cA01 = add2(cA01, kA01[rr]); cA23 = add2(cA23, kA23[rr]);
            cB01 = add2(cB01, kB01[rr]); cB23 = add2(cB23, kB23[rr]);
        }
        *(ull*)&sm.temp[warp][lane*4]       = cA01;
        *(ull*)&sm.temp[warp][lane*4 + 2]   = cA23;
        *(ull*)&sm.temp[warp][lane*4 + 128] = cB01;
        *(ull*)&sm.temp[warp][lane*4 + 130] = cB23;
    }
    __syncthreads();

    // ---- Sinkhorn iterations ----
    for (int t = 1; t <= SK_ITERS; ++t) {
        const int  buf  = t & 1;
        const bool last = (t == SK_ITERS);

        // step 1: cross-warp colsum reduce (packed, 128 threads); export + sumA
        if (tid < 128) {
            ull mp = 0;
            #pragma unroll
            for (int w = 0; w < NWARPS; ++w)
                mp = add2(mp, *(const ull*)&sm.temp[w][2 * tid]);
            *(ull*)&sm.expt[buf][2 * tid] = mp;
        } else if (tid < 160) {                       // warp 4: sumA over own 64 a's
            int l = tid - 128;
            float s = sm.a[l] + sm.a[l + 32];
            #pragma unroll
            for (int o = 16; o; o >>= 1) s += __shfl_down_sync(0xffffffffu, s, o);
            if (l == 0) sm.expt[buf][WW] = s;
        }
        asm volatile("barrier.cluster.arrive.aligned;" ::: "memory");
        asm volatile("barrier.cluster.wait.aligned;"   ::: "memory");

        // step 2: full colsum over 4 ranks (fixed order) + dustbin; b = nu/colsum
        const float aWv = sm.aW;
        if (tid < 128) {
            const unsigned off = (unsigned)buf * 1056u + (unsigned)tid * 8u;
            ull c01 = add2(add2(ldsc64(eaddr[0] + off), ldsc64(eaddr[1] + off)),
                           add2(ldsc64(eaddr[2] + off), ldsc64(eaddr[3] + off)));
            float clo, chi; upk2(c01, clo, chi);
            float paw = p * aWv;
            float b0 = __fdividef(inv2w, clo + paw);
            float b1 = __fdividef(inv2w, chi + paw);
            *(ull*)&sm.b[2 * tid] = pk2(b0, b1);
            float s = b0 + b1;
            #pragma unroll
            for (int o = 16; o; o >>= 1) s += __shfl_down_sync(0xffffffffu, s, o);
            if (lane == 0) sm.wsum[warp] = s;
        } else if (tid == 128) {                      // dustbin column
            const unsigned offA = (unsigned)buf * 1056u + 1024u;
            float sumA = (ldsc32(eaddr[0] + offA) + ldsc32(eaddr[1] + offA)) +
                         (ldsc32(eaddr[2] + offA) + ldsc32(eaddr[3] + offA));
            sm.bW = 0.5f / (p * (sumA + aWv));
        }
        __syncthreads();
        if (tid == 0) {                               // dustbin row -> next aW
            float sb = (sm.wsum[0] + sm.wsum[1]) + (sm.wsum[2] + sm.wsum[3]);
            sm.aW = 0.5f / (p * (sb + sm.bW));
        }

        // step 3: register sweep: rowsum -> a[i]; next colsum partials
        const float pbW = p * sm.bW;
        ull bA01 = *(const ull*)&sm.b[lane*4];
        ull bA23 = *(const ull*)&sm.b[lane*4 + 2];
        ull bB01 = *(const ull*)&sm.b[lane*4 + 128];
        ull bB23 = *(const ull*)&sm.b[lane*4 + 130];

        if (!last) {
            ull cA01 = 0, cA23 = 0, cB01 = 0, cB23 = 0;
            #pragma unroll
            for (int rr = 0; rr < 4; ++rr) {
                int i = warp * 4 + rr;
                ull r01 = mul2(kA01[rr], bA01);
                r01 = fma2(kB01[rr], bB01, r01);
                ull r23 = mul2(kA23[rr], bA23);
                r23 = fma2(kB23[rr], bB23, r23);
                float rlo, rhi; upk2(add2(r01, r23), rlo, rhi);
                float rs = rlo + rhi;
                #pragma unroll
                for (int o = 16; o; o >>= 1) rs += __shfl_xor_sync(0xffffffffu, rs, o);
                float ai = __fdividef(inv2w, rs + pbW);
                if (lane == 0) sm.a[i] = ai;
                ull ai2 = pk2(ai, ai);
                cA01 = fma2(kA01[rr], ai2, cA01);
                cA23 = fma2(kA23[rr], ai2, cA23);
                cB01 = fma2(kB01[rr], ai2, cB01);
                cB23 = fma2(kB23[rr], ai2, cB23);
            }
            *(ull*)&sm.temp[warp][lane*4]       = cA01;
            *(ull*)&sm.temp[warp][lane*4 + 2]   = cA23;
            *(ull*)&sm.temp[warp][lane*4 + 128] = cB01;
            *(ull*)&sm.temp[warp][lane*4 + 130] = cB23;
        } else {
            // final iteration: argmax + 3-tap soft-argmax readout
            #pragma unroll
            for (int rr = 0; rr < 4; ++rr) {
                int i  = warp * 4 + rr;
                int ig = (int)rank * RPC + i;
                float va0, va1, va2, va3, vb0, vb1, vb2, vb3;
                upk2(mul2(kA01[rr], bA01), va0, va1);
                upk2(mul2(kA23[rr], bA23), va2, va3);
                upk2(mul2(kB01[rr], bB01), vb0, vb1);
                upk2(mul2(kB23[rr], bB23), vb2, vb3);
                float rs = ((va0 + va1) + (va2 + va3)) + ((vb0 + vb1) + (vb2 + vb3));
                #pragma unroll
                for (int o = 16; o; o >>= 1) rs += __shfl_xor_sync(0xffffffffu, rs, o);
                float ai = __fdividef(inv2w, rs + pbW);

                float best = va0; int bestj = lane * 4;
                if (va1 > best) { best = va1; bestj = lane*4 + 1; }
                if (va2 > best) { best = va2; bestj = lane*4 + 2; }
                if (va3 > best) { best = va3; bestj = lane*4 + 3; }
                int jb = lane * 4 + 128;
                if (vb0 > best) { best = vb0; bestj = jb;     }
                if (vb1 > best) { best = vb1; bestj = jb + 1; }
                if (vb2 > best) { best = vb2; bestj = jb + 2; }
                if (vb3 > best) { best = vb3; bestj = jb + 3; }
                #pragma unroll
                for (int o = 16; o; o >>= 1) {        // first-index tie-break
                    float ov = __shfl_xor_sync(0xffffffffu, best, o);
                    int   oj = __shfl_xor_sync(0xffffffffu, bestj, o);
                    if (ov > best || (ov == best && oj < bestj)) { best = ov; bestj = oj; }
                }

                float scale = ai * 512.0f;            // attn = 2w * a_i * (K*b)
                float nl = 0.0f, dl = 0.0f;
                #pragma unroll
                for (int d = -1; d <= 1; ++d) {
                    int jj = bestj + d;
                    if (jj < 0 || jj >= WW) continue;
                    int cA = jj - lane * 4;
                    int cB = jj - 128 - lane * 4;
                    float v = 0.0f; bool own = false;
                    if (cA >= 0 && cA < 4) {
                        v = (cA == 0) ? va0 : (cA == 1) ? va1 : (cA == 2) ? va2 : va3;
                        own = true;
                    } else if (cB >= 0 && cB < 4) {
                        v = (cB == 0) ? vb0 : (cB == 1) ? vb1 : (cB == 2) ? vb2 : vb3;
                        own = true;
                    }
                    if (own) {
                        float av = v * scale;
                        nl += av;
                        dl += av * fmaxf((float)(ig - jj), 0.0f);
                    }
                }
                #pragma unroll
                for (int o = 16; o; o >>= 1) {
                    nl += __shfl_xor_sync(0xffffffffu, nl, o);
                    dl += __shfl_xor_sync(0xffffffffu, dl, o);
                }
                if (lane == 0) {
                    float normc = (nl < 0.1f) ? 1.0f : nl;
                    size_t o0 = (size_t)m * WW + (size_t)ig;
                    out[o0] = __fdividef(dl, normc);              // disp
                    out[(size_t)out_half + o0] = 1.0f - normc;    // occ
                }
            }
        }
        __syncthreads();
    }

    // keep smem alive until peers finish their last DSMEM reads
    asm volatile("barrier.cluster.arrive.aligned;" ::: "memory");
    asm volatile("barrier.cluster.wait.aligned;"   ::: "memory");
}

extern "C" void kernel_launch(void* const* d_in, const int* in_sizes, int n_in,
                              void* d_out, int out_size) {
    const float* attn = (const float*)d_in[0];
    const float* phi  = (const float*)d_in[1];
    float* out        = (float*)d_out;

    int NH = in_sizes[0] / (WW * WW);           // 480 matrices
    sinkhorn_disp_kernel<<<CSZ * NH, NTHREADS>>>(attn, phi, out, out_size / 2);
}